// round 14
// baseline (speedup 1.0000x reference)
#include <cuda_runtime.h>
#include <cuda_fp16.h>
#include <cstdint>

#define BB 64
#define TT 1024
#define CC 512
#define HH 256
#define NE 30
#define STEPS 501
#define NG 1024          // gemm output cols: 768 gates + 256 gh_n
#define WROWS 800        // wcat rows: 512 ctx + 30 onehot + 256 hidden + 2 pad
#define HT 512           // T half per CTA

// ---------------- static scratch (no allocation) ----------------
__device__ __align__(16) __half d_proj_h[(size_t)BB * TT * HH];  // 32 MB
__device__ __align__(16) __half d_fea_h[(size_t)BB * CC * TT];   // 64 MB
__device__ __align__(16) __half d_wcat_h[WROWS * NG];            // 1.6 MB
__device__ __align__(16) __half d_hw_h[3 * HH * HH];             // sg1 | lg1 | h2h
// cross-CTA exchange (parity double-buffered) + flags
__device__ __align__(16) float d_xv[2][BB][2][516];              // ctx partial + m,S
__device__ __align__(16) float d_xg[2][BB][2][512];              // gemm halves
__device__ int d_flag[BB][2][2];                                 // [b][p][phase]

__device__ __forceinline__ void h8_to_f(uint4 v, float* f) {
    const __half2* p = (const __half2*)&v;
    #pragma unroll
    for (int i = 0; i < 4; i++) { float2 t = __half22float2(p[i]); f[2*i] = t.x; f[2*i+1] = t.y; }
}
// packed f32x2 fma (Blackwell; ptxas never auto-fuses this)
__device__ __forceinline__ float2 f2fma(float2 a, float2 b, float2 c) {
    unsigned long long ua, ub, uc, ud;
    ua = *(unsigned long long*)&a; ub = *(unsigned long long*)&b; uc = *(unsigned long long*)&c;
    asm("fma.rn.f32x2 %0, %1, %2, %3;" : "=l"(ud) : "l"(ua), "l"(ub), "l"(uc));
    return *(float2*)&ud;
}
// release-store / acquire-load flag ops (no CCTL.IVALL, unlike __threadfence)
__device__ __forceinline__ void sigrel(int* p, int v) {
    asm volatile("st.release.gpu.global.b32 [%0], %1;" :: "l"(p), "r"(v) : "memory");
}
__device__ __forceinline__ int ldacq(const int* p) {
    int v; asm volatile("ld.acquire.gpu.global.b32 %0, [%1];" : "=r"(v) : "l"(p) : "memory");
    return v;
}

// ---------------- setup: fp16 Wcat + head weights + flag reset ----------------
__global__ void k_setup(const float* __restrict__ w_ih, const float* __restrict__ w_hh,
                        const float* __restrict__ sg1_w, const float* __restrict__ lg1_w,
                        const float* __restrict__ h2h_w) {
    int idx = blockIdx.x * 256 + threadIdx.x;
    if (idx < BB * 2 * 2) ((int*)d_flag)[idx] = 0;
    if (idx < WROWS * NG) {
        int k = idx >> 10, j = idx & 1023;
        float v = 0.f;
        if (j < 768) {
            if (k < 542)      v = w_ih[k * 768 + j];
            else if (k < 798) v = w_hh[(k - 542) * 768 + j];
        } else {
            if (k >= 542 && k < 798) v = w_hh[(k - 542) * 768 + 512 + (j - 768)];
        }
        d_wcat_h[idx] = __float2half(v);
    }
    int idx2 = idx - WROWS * NG;
    if (idx2 >= 0 && idx2 < 3 * HH * HH) {
        int mm = idx2 >> 16, i = idx2 & 65535;
        const float* w = (mm == 0) ? sg1_w : (mm == 1) ? lg1_w : h2h_w;
        d_hw_h[idx2] = __float2half(w[i]);
    }
}

// ---------------- fea -> fp16 ----------------
__global__ __launch_bounds__(256) void k_conv(const float* __restrict__ fea) {
    size_t i = ((size_t)blockIdx.x * 256 + threadIdx.x) * 4;
    if (i >= (size_t)BB * CC * TT) return;
    float4 v = *(const float4*)&fea[i];
    *(__half2*)&d_fea_h[i]     = __floats2half2_rn(v.x, v.y);
    *(__half2*)&d_fea_h[i + 2] = __floats2half2_rn(v.z, v.w);
}

// ---------------- proj[b,t,h] = sum_c fea[b,c,t] * i2h_w[c,h] ----------------
__global__ __launch_bounds__(256) void k_proj(const float* __restrict__ fea,
                                              const float* __restrict__ i2h_w) {
    int t0 = blockIdx.x * 64, h0 = blockIdx.y * 64, b = blockIdx.z;
    __shared__ float As[8][64];
    __shared__ float Bs[8][64];
    int tid = threadIdx.x;
    int tx = tid & 15, ty = tid >> 4;
    float acc[4][4] = {};
    for (int k0 = 0; k0 < CC; k0 += 8) {
        #pragma unroll
        for (int r = 0; r < 2; r++) {
            int i = tid + r * 256;
            int kk = i >> 6, m = i & 63;
            As[kk][m] = fea[((size_t)b * CC + (k0 + kk)) * TT + t0 + m];
            Bs[kk][m] = i2h_w[(k0 + kk) * HH + h0 + m];
        }
        __syncthreads();
        #pragma unroll
        for (int kk = 0; kk < 8; kk++) {
            float a[4], bv[4];
            #pragma unroll
            for (int i = 0; i < 4; i++) a[i] = As[kk][ty * 4 + i];
            #pragma unroll
            for (int j = 0; j < 4; j++) bv[j] = Bs[kk][tx * 4 + j];
            #pragma unroll
            for (int i = 0; i < 4; i++)
                #pragma unroll
                for (int j = 0; j < 4; j++) acc[i][j] += a[i] * bv[j];
        }
        __syncthreads();
    }
    #pragma unroll
    for (int i = 0; i < 4; i++) {
        size_t base = ((size_t)b * TT + t0 + ty * 4 + i) * HH + h0 + tx * 4;
        *(__half2*)&d_proj_h[base]     = __floats2half2_rn(acc[i][0], acc[i][1]);
        *(__half2*)&d_proj_h[base + 2] = __floats2half2_rn(acc[i][2], acc[i][3]);
    }
}

// ---------------- decode: 2 CTAs per batch (T-split + col-split) ----------------
__global__ __launch_bounds__(1024, 1) void k_decode(
    const int* __restrict__ targets,
    const float* __restrict__ score_w,
    const float* __restrict__ b_ih, const float* __restrict__ b_hh,
    const float* __restrict__ sg1_b, const float* __restrict__ sg2_w,
    const float* __restrict__ sg2_b, const float* __restrict__ lg1_b,
    const float* __restrict__ lg2_w, const float* __restrict__ lg2_b,
    const float* __restrict__ h2h_b,
    float* __restrict__ out)
{
    __shared__ __align__(16) float  s_w[HT];      // raw scores e
    __shared__ __align__(16) __half s_wh[HT];     // unnormalized exp weights (fp16)
    __shared__ __align__(16) float  s_ctx[CC];
    __shared__ __align__(16) float  s_hid[HH];
    __shared__ __align__(16) float  s_ph[HH];
    __shared__ __align__(16) float  s_g[NG];
    __shared__ __align__(16) float  s_scr[6144];  // 24 KB partials (gemm 12x512 / heads)
    __shared__ __align__(16) float  s_s1[HH];
    __shared__ float s_red[64];
    __shared__ float s_mS[2];

    int b = blockIdx.x >> 1, p = blockIdx.x & 1, q = 1 - p;
    int tid = threadIdx.x, wid = tid >> 5, lane = tid & 31;
    const __half* w_g1  = d_hw_h + (size_t)p * HH * HH;       // sg1 (p=0) / lg1 (p=1)
    const __half* w_h2h = d_hw_h + (size_t)2 * HH * HH;
    const float*  b_g1  = p ? lg1_b : sg1_b;

    if (tid < HH) { s_hid[tid] = 0.f; s_ph[tid] = h2h_b[tid]; }   // h0=0 -> ph=bias
    float rsw[8];
    #pragma unroll
    for (int i = 0; i < 8; i++) rsw[i] = score_w[lane * 8 + i];
    __syncthreads();

    for (int s = 0; s < STEPS; s++) {
        int ch = targets[b * STEPS + s];
        int par = s & 1;
        __half2 rph2[4];
        #pragma unroll
        for (int i = 0; i < 4; i++)
            rph2[i] = __floats2half2_rn(s_ph[lane * 8 + 2*i], s_ph[lane * 8 + 2*i + 1]);

        // ---- scores for t in [p*HT, p*HT+HT): 32 warps x 16 t, f16x2 tanh ----
        const uint4* pbase =
            (const uint4*)&d_proj_h[((size_t)b * TT + p * HT + wid * 16) * HH + lane * 8];
        #pragma unroll 4
        for (int tt = 0; tt < 16; tt++) {
            uint4 pv = pbase[(size_t)tt * (HH / 8)];
            const __half2* ph2 = (const __half2*)&pv;
            float a = 0.f;
            #pragma unroll
            for (int i = 0; i < 4; i++) {
                __half2 x = __hadd2(ph2[i], rph2[i]);
                unsigned xr = *(unsigned*)&x, th;
                asm("tanh.approx.f16x2 %0, %1;" : "=r"(th) : "r"(xr));
                float2 tf = __half22float2(*(__half2*)&th);
                a += tf.x * rsw[2*i] + tf.y * rsw[2*i + 1];
            }
            #pragma unroll
            for (int o = 16; o; o >>= 1) a += __shfl_xor_sync(~0u, a, o);
            if (lane == 0) s_w[wid * 16 + tt] = a;
        }
        __syncthreads();

        // ---- local softmax stats (m, S); unnormalized weights -> fp16 ----
        float e = (tid < HT) ? s_w[tid] : -3.4e38f;
        float m = e;
        #pragma unroll
        for (int o = 16; o; o >>= 1) m = fmaxf(m, __shfl_xor_sync(~0u, m, o));
        if (lane == 0) s_red[wid] = m;
        __syncthreads();
        m = s_red[0];
        #pragma unroll
        for (int i = 1; i < 16; i++) m = fmaxf(m, s_red[i]);
        float ex = (tid < HT) ? __expf(e - m) : 0.f;
        if (tid < HT) s_wh[tid] = __float2half(ex);
        float sm = ex;
        #pragma unroll
        for (int o = 16; o; o >>= 1) sm += __shfl_xor_sync(~0u, sm, o);
        if (lane == 0) s_red[32 + wid] = sm;
        __syncthreads();
        if (tid == 0) {
            float t = 0.f;
            #pragma unroll
            for (int i = 0; i < 16; i++) t += s_red[32 + i];
            s_mS[0] = m; s_mS[1] = t;
        }
        __syncthreads();

        // ---- partial ctx: v[c] = sum_{t half} w[t] * fea[b,c,p*HT+t] ----
        #pragma unroll 1
        for (int cc = 0; cc < 16; cc++) {
            int c = wid * 16 + cc;
            const __half* f = &d_fea_h[((size_t)b * CC + c) * TT + p * HT];
            float2 acc2 = {0.f, 0.f};
            #pragma unroll
            for (int qq = 0; qq < 2; qq++) {
                int t = qq * 256 + lane * 8;
                uint4 fv = *(const uint4*)&f[t];
                uint4 av = *(const uint4*)&s_wh[t];       // conflict-free 16B stride
                const __half2* fh = (const __half2*)&fv;
                const __half2* ah = (const __half2*)&av;
                #pragma unroll
                for (int i = 0; i < 4; i++)
                    acc2 = f2fma(__half22float2(fh[i]), __half22float2(ah[i]), acc2);
            }
            float acc = acc2.x + acc2.y;
            #pragma unroll
            for (int o = 16; o; o >>= 1) acc += __shfl_xor_sync(~0u, acc, o);
            if (lane == 0) s_ctx[c] = acc;
        }
        __syncthreads();

        // ---- exchange 1: (v, m, S) via release/acquire ----
        {
            float* buf = &d_xv[par][b][p][0];
            if (tid < HT) buf[tid] = s_ctx[tid];
            if (tid == 0) { buf[512] = s_mS[0]; buf[513] = s_mS[1]; }
            __syncthreads();
            if (tid == 0) {
                sigrel(&d_flag[b][p][0], s + 1);
                while (ldacq(&d_flag[b][q][0]) < s + 1) {}
            }
            __syncthreads();
            const float* pb = &d_xv[par][b][q][0];
            float mpeer = __ldcg(&pb[512]), Speer = __ldcg(&pb[513]);
            float mloc = s_mS[0], Sloc = s_mS[1];
            float m0 = p ? mpeer : mloc, S0 = p ? Speer : Sloc;
            float m1 = p ? mloc : mpeer, S1 = p ? Sloc : Speer;
            float M  = fmaxf(m0, m1);
            float f0 = __expf(m0 - M), f1 = __expf(m1 - M);
            float inv = 1.f / (S0 * f0 + S1 * f1);
            float w0 = f0 * inv, w1 = f1 * inv;
            if (tid < HT) {
                float vpeer = __ldcg(&pb[tid]);
                float v0 = p ? vpeer : s_ctx[tid];
                float v1 = p ? s_ctx[tid] : vpeer;
                s_ctx[tid] = v0 * w0 + v1 * w1;   // identical in both CTAs
            }
        }
        __syncthreads();

        // ---- GRU gemm half: n in [p*512,+512), 12-way k-split, 8 cols/thread ----
        if (tid < 768) {
            int kg = tid >> 6, nn = tid & 63, n = p * 512 + nn * 8;
            float2 a01 = {0,0}, a23 = {0,0}, a45 = {0,0}, a67 = {0,0};
            int k0 = kg * 64;
            #pragma unroll 8
            for (int k = k0; k < k0 + 64; k++) {
                int row  = (k < 512) ? k : k + 30;          // skip onehot rows
                float uv = (k < 512) ? s_ctx[k] : s_hid[k - 512];
                float2 u2 = make_float2(uv, uv);
                uint4 wv = *(const uint4*)&d_wcat_h[(size_t)row * NG + n];
                const __half2* wh = (const __half2*)&wv;
                a01 = f2fma(u2, __half22float2(wh[0]), a01);
                a23 = f2fma(u2, __half22float2(wh[1]), a23);
                a45 = f2fma(u2, __half22float2(wh[2]), a45);
                a67 = f2fma(u2, __half22float2(wh[3]), a67);
            }
            *(float4*)&s_scr[kg * 512 + nn * 8]     = make_float4(a01.x, a01.y, a23.x, a23.y);
            *(float4*)&s_scr[kg * 512 + nn * 8 + 4] = make_float4(a45.x, a45.y, a67.x, a67.y);
        }
        __syncthreads();
        if (tid < 512) {
            float g = __half2float(d_wcat_h[(size_t)(512 + ch) * NG + p * 512 + tid]);
            #pragma unroll
            for (int kg = 0; kg < 12; kg++) g += s_scr[kg * 512 + tid];
            s_g[p * 512 + tid] = g;
            d_xg[par][b][p][tid] = g;
        }
        __syncthreads();

        // ---- exchange 2: g halves ----
        if (tid == 0) {
            sigrel(&d_flag[b][p][1], s + 1);
            while (ldacq(&d_flag[b][q][1]) < s + 1) {}
        }
        __syncthreads();
        if (tid < 512) s_g[q * 512 + tid] = __ldcg(&d_xg[par][b][q][tid]);
        __syncthreads();

        // ---- gates (redundant in both CTAs -> identical s_hid) ----
        if (tid < HH) {
            int h = tid;
            float gr  = s_g[h]       + b_ih[h]       + b_hh[h];
            float gz  = s_g[256 + h] + b_ih[256 + h] + b_hh[256 + h];
            float ghn = s_g[768 + h] + b_hh[512 + h];
            float gxn = (s_g[512 + h] - s_g[768 + h]) + b_ih[512 + h];
            float r = 1.f / (1.f + expf(-gr));
            float z = 1.f / (1.f + expf(-gz));
            float n = tanhf(gxn + r * ghn);
            s_hid[h] = (1.f - z) * n + z * s_hid[h];
        }
        __syncthreads();

        // ---- heads: (sg1|lg1) + h2h matvec, 8-way k-split, 8 cols/thread ----
        if (tid < 512) {
            int mm = tid >> 8, idx = tid & 255, kq = idx >> 5, hg = idx & 31;
            const __half* w = (mm == 0) ? w_g1 : w_h2h;
            int n = hg * 8, k0 = kq * 32;
            float2 a01 = {0,0}, a23 = {0,0}, a45 = {0,0}, a67 = {0,0};
            #pragma unroll 8
            for (int k = k0; k < k0 + 32; k++) {
                float hv = s_hid[k];
                float2 h2 = make_float2(hv, hv);
                uint4 wv = *(const uint4*)&w[k * HH + n];
                const __half2* wh = (const __half2*)&wv;
                a01 = f2fma(h2, __half22float2(wh[0]), a01);
                a23 = f2fma(h2, __half22float2(wh[1]), a23);
                a45 = f2fma(h2, __half22float2(wh[2]), a45);
                a67 = f2fma(h2, __half22float2(wh[3]), a67);
            }
            *(float4*)&s_scr[mm * 2048 + kq * 256 + n]     = make_float4(a01.x, a01.y, a23.x, a23.y);
            *(float4*)&s_scr[mm * 2048 + kq * 256 + n + 4] = make_float4(a45.x, a45.y, a67.x, a67.y);
        }
        __syncthreads();
        if (tid < 512) {
            int mm = tid >> 8, h = tid & 255;
            float v = 0.f;
            #pragma unroll
            for (int kq = 0; kq < 8; kq++) v += s_scr[mm * 2048 + kq * 256 + h];
            if (mm == 0) s_s1[h] = v + b_g1[h];
            else         s_ph[h] = v + h2h_b[h];    // redundant in both CTAs
        }
        __syncthreads();

        // ---- output heads: 16 threads per output element ----
        if (p == 0) {
            if (tid < 16 * NE) {
                int g = tid >> 4, l = tid & 15;
                float sv = 0.f;
                #pragma unroll
                for (int j = 0; j < 16; j++) {
                    int k = l + j * 16;
                    sv += s_s1[k] * sg2_w[k * NE + g];
                }
                #pragma unroll
                for (int o = 8; o; o >>= 1) sv += __shfl_xor_sync(~0u, sv, o);
                if (l == 0) out[((size_t)b * STEPS + s) * NE + g] = sv + sg2_b[g];
            }
        } else {
            if (tid < 64) {
                int g = tid >> 4, l = tid & 15;
                float lv = 0.f;
                #pragma unroll
                for (int j = 0; j < 16; j++) {
                    int k = l + j * 16;
                    lv += s_s1[k] * lg2_w[k * 4 + g];
                }
                #pragma unroll
                for (int o = 8; o; o >>= 1) lv += __shfl_xor_sync(~0u, lv, o);
                if (l == 0)
                    out[(size_t)BB * STEPS * NE + ((size_t)b * STEPS + s) * 4 + g] =
                        1.f / (1.f + expf(-(lv + lg2_b[g])));
            }
        }
        __syncthreads();
    }
}

// ---------------- launch ----------------
extern "C" void kernel_launch(void* const* d_in, const int* in_sizes, int n_in,
                              void* d_out, int out_size) {
    const float* fea      = (const float*)d_in[0];
    const int*   targets  = (const int*)  d_in[1];
    const float* i2h_w    = (const float*)d_in[2];
    const float* h2h_w    = (const float*)d_in[3];
    const float* h2h_b    = (const float*)d_in[4];
    const float* score_w  = (const float*)d_in[5];
    const float* gru_w_ih = (const float*)d_in[6];
    const float* gru_w_hh = (const float*)d_in[7];
    const float* gru_b_ih = (const float*)d_in[8];
    const float* gru_b_hh = (const float*)d_in[9];
    const float* sg1_w    = (const float*)d_in[10];
    const float* sg1_b    = (const float*)d_in[11];
    const float* sg2_w    = (const float*)d_in[12];
    const float* sg2_b    = (const float*)d_in[13];
    const float* lg1_w    = (const float*)d_in[14];
    const float* lg1_b    = (const float*)d_in[15];
    const float* lg2_w    = (const float*)d_in[16];
    const float* lg2_b    = (const float*)d_in[17];
    float* out = (float*)d_out;

    int setup_elems = WROWS * NG + 3 * HH * HH;
    k_setup<<<(setup_elems + 255) / 256, 256>>>(gru_w_ih, gru_w_hh, sg1_w, lg1_w, h2h_w);
    k_conv<<<(int)(((size_t)BB * CC * TT / 4 + 255) / 256), 256>>>(fea);
    k_proj<<<dim3(TT / 64, HH / 64, BB), 256>>>(fea, i2h_w);
    k_decode<<<BB * 2, 1024>>>(targets, score_w,
                               gru_b_ih, gru_b_hh,
                               sg1_b, sg2_w, sg2_b,
                               lg1_b, lg2_w, lg2_b,
                               h2h_b, out);
}

// round 15
// speedup vs baseline: 1.4124x; 1.4124x over previous
#include <cuda_runtime.h>
#include <cuda_fp16.h>
#include <cstdint>

#define BB 64
#define TT 1024
#define CC 512
#define HH 256
#define NE 30
#define STEPS 501
#define NG 1024          // gemm output cols: 768 gates + 256 gh_n
#define WROWS 800        // wcat rows: 512 ctx + 30 onehot + 256 hidden + 2 pad
#define HT 512           // T half per CTA

// ---------------- static scratch (no allocation) ----------------
__device__ __align__(16) __half d_proj_h[(size_t)BB * TT * HH];  // 32 MB
__device__ __align__(16) __half d_fea_h[(size_t)BB * CC * TT];   // 64 MB
__device__ __align__(16) __half d_wcat_h[WROWS * NG];            // 1.6 MB
__device__ __align__(16) __half d_hw_h[3 * HH * HH];             // sg1 | lg1 | h2h
// cross-CTA exchange (parity double-buffered) + flags
__device__ __align__(16) float d_xv[2][BB][2][516];              // ctx partial + m,S
__device__ __align__(16) float d_xg[2][BB][2][512];              // gemm halves
__device__ int d_flag[BB][2][2];                                 // [b][p][phase]

__device__ __forceinline__ void h8_to_f(uint4 v, float* f) {
    const __half2* p = (const __half2*)&v;
    #pragma unroll
    for (int i = 0; i < 4; i++) { float2 t = __half22float2(p[i]); f[2*i] = t.x; f[2*i+1] = t.y; }
}
// release-store / acquire-load flag ops (no CCTL.IVALL, unlike __threadfence)
__device__ __forceinline__ void sigrel(int* p, int v) {
    asm volatile("st.release.gpu.global.b32 [%0], %1;" :: "l"(p), "r"(v) : "memory");
}
__device__ __forceinline__ int ldacq(const int* p) {
    int v; asm volatile("ld.acquire.gpu.global.b32 %0, [%1];" : "=r"(v) : "l"(p) : "memory");
    return v;
}

// ---------------- setup: fp16 Wcat + head weights + flag reset ----------------
__global__ void k_setup(const float* __restrict__ w_ih, const float* __restrict__ w_hh,
                        const float* __restrict__ sg1_w, const float* __restrict__ lg1_w,
                        const float* __restrict__ h2h_w) {
    int idx = blockIdx.x * 256 + threadIdx.x;
    if (idx < BB * 2 * 2) ((int*)d_flag)[idx] = 0;
    if (idx < WROWS * NG) {
        int k = idx >> 10, j = idx & 1023;
        float v = 0.f;
        if (j < 768) {
            if (k < 542)      v = w_ih[k * 768 + j];
            else if (k < 798) v = w_hh[(k - 542) * 768 + j];
        } else {
            if (k >= 542 && k < 798) v = w_hh[(k - 542) * 768 + 512 + (j - 768)];
        }
        d_wcat_h[idx] = __float2half(v);
    }
    int idx2 = idx - WROWS * NG;
    if (idx2 >= 0 && idx2 < 3 * HH * HH) {
        int mm = idx2 >> 16, i = idx2 & 65535;
        const float* w = (mm == 0) ? sg1_w : (mm == 1) ? lg1_w : h2h_w;
        d_hw_h[idx2] = __float2half(w[i]);
    }
}

// ---------------- fea -> fp16 ----------------
__global__ __launch_bounds__(256) void k_conv(const float* __restrict__ fea) {
    size_t i = ((size_t)blockIdx.x * 256 + threadIdx.x) * 4;
    if (i >= (size_t)BB * CC * TT) return;
    float4 v = *(const float4*)&fea[i];
    *(__half2*)&d_fea_h[i]     = __floats2half2_rn(v.x, v.y);
    *(__half2*)&d_fea_h[i + 2] = __floats2half2_rn(v.z, v.w);
}

// ---------------- proj[b,t,h] = sum_c fea[b,c,t] * i2h_w[c,h] ----------------
__global__ __launch_bounds__(256) void k_proj(const float* __restrict__ fea,
                                              const float* __restrict__ i2h_w) {
    int t0 = blockIdx.x * 64, h0 = blockIdx.y * 64, b = blockIdx.z;
    __shared__ float As[8][64];
    __shared__ float Bs[8][64];
    int tid = threadIdx.x;
    int tx = tid & 15, ty = tid >> 4;
    float acc[4][4] = {};
    for (int k0 = 0; k0 < CC; k0 += 8) {
        #pragma unroll
        for (int r = 0; r < 2; r++) {
            int i = tid + r * 256;
            int kk = i >> 6, m = i & 63;
            As[kk][m] = fea[((size_t)b * CC + (k0 + kk)) * TT + t0 + m];
            Bs[kk][m] = i2h_w[(k0 + kk) * HH + h0 + m];
        }
        __syncthreads();
        #pragma unroll
        for (int kk = 0; kk < 8; kk++) {
            float a[4], bv[4];
            #pragma unroll
            for (int i = 0; i < 4; i++) a[i] = As[kk][ty * 4 + i];
            #pragma unroll
            for (int j = 0; j < 4; j++) bv[j] = Bs[kk][tx * 4 + j];
            #pragma unroll
            for (int i = 0; i < 4; i++)
                #pragma unroll
                for (int j = 0; j < 4; j++) acc[i][j] += a[i] * bv[j];
        }
        __syncthreads();
    }
    #pragma unroll
    for (int i = 0; i < 4; i++) {
        size_t base = ((size_t)b * TT + t0 + ty * 4 + i) * HH + h0 + tx * 4;
        *(__half2*)&d_proj_h[base]     = __floats2half2_rn(acc[i][0], acc[i][1]);
        *(__half2*)&d_proj_h[base + 2] = __floats2half2_rn(acc[i][2], acc[i][3]);
    }
}

// ---------------- decode: 2 CTAs per batch (T-split + col-split) ----------------
__global__ __launch_bounds__(1024, 1) void k_decode(
    const int* __restrict__ targets,
    const float* __restrict__ score_w,
    const float* __restrict__ b_ih, const float* __restrict__ b_hh,
    const float* __restrict__ sg1_b, const float* __restrict__ sg2_w,
    const float* __restrict__ sg2_b, const float* __restrict__ lg1_b,
    const float* __restrict__ lg2_w, const float* __restrict__ lg2_b,
    const float* __restrict__ h2h_b,
    float* __restrict__ out)
{
    __shared__ __align__(16) float  s_w[HT];      // raw scores e
    __shared__ __align__(16) __half s_wh[HT];     // unnormalized exp weights (fp16)
    __shared__ __align__(16) float  s_ctx[CC];
    __shared__ __align__(16) float  s_hid[HH];
    __shared__ __align__(16) float  s_ph[HH];
    __shared__ __align__(16) float  s_g[NG];
    __shared__ __align__(16) float  s_scr[4096];  // 16 KB partials (gemm / heads)
    __shared__ __align__(16) float  s_s1[HH];
    __shared__ float s_red[64];
    __shared__ float s_mS[2];

    int b = blockIdx.x >> 1, p = blockIdx.x & 1, q = 1 - p;
    int tid = threadIdx.x, wid = tid >> 5, lane = tid & 31;
    const __half* w_g1  = d_hw_h + (size_t)p * HH * HH;       // sg1 (p=0) / lg1 (p=1)
    const __half* w_h2h = d_hw_h + (size_t)2 * HH * HH;
    const float*  b_g1  = p ? lg1_b : sg1_b;

    if (tid < HH) { s_hid[tid] = 0.f; s_ph[tid] = h2h_b[tid]; }   // h0=0 -> ph=bias
    float rsw[8];
    #pragma unroll
    for (int i = 0; i < 8; i++) rsw[i] = score_w[lane * 8 + i];
    __syncthreads();

    for (int s = 0; s < STEPS; s++) {
        int ch = targets[b * STEPS + s];
        int par = s & 1;
        __half2 rph2[4];
        #pragma unroll
        for (int i = 0; i < 4; i++)
            rph2[i] = __floats2half2_rn(s_ph[lane * 8 + 2*i], s_ph[lane * 8 + 2*i + 1]);

        // ---- scores for t in [p*HT, p*HT+HT): 32 warps x 16 t, f16x2 tanh ----
        const uint4* pbase =
            (const uint4*)&d_proj_h[((size_t)b * TT + p * HT + wid * 16) * HH + lane * 8];
        #pragma unroll 4
        for (int tt = 0; tt < 16; tt++) {
            uint4 pv = pbase[(size_t)tt * (HH / 8)];
            const __half2* ph2 = (const __half2*)&pv;
            float a = 0.f;
            #pragma unroll
            for (int i = 0; i < 4; i++) {
                __half2 x = __hadd2(ph2[i], rph2[i]);
                unsigned xr = *(unsigned*)&x, th;
                asm("tanh.approx.f16x2 %0, %1;" : "=r"(th) : "r"(xr));
                float2 tf = __half22float2(*(__half2*)&th);
                a += tf.x * rsw[2*i] + tf.y * rsw[2*i + 1];
            }
            #pragma unroll
            for (int o = 16; o; o >>= 1) a += __shfl_xor_sync(~0u, a, o);
            if (lane == 0) s_w[wid * 16 + tt] = a;
        }
        __syncthreads();

        // ---- local softmax stats (m, S); unnormalized weights -> fp16 ----
        float e = (tid < HT) ? s_w[tid] : -3.4e38f;
        float m = e;
        #pragma unroll
        for (int o = 16; o; o >>= 1) m = fmaxf(m, __shfl_xor_sync(~0u, m, o));
        if (lane == 0) s_red[wid] = m;
        __syncthreads();
        m = s_red[0];
        #pragma unroll
        for (int i = 1; i < 16; i++) m = fmaxf(m, s_red[i]);
        float ex = (tid < HT) ? __expf(e - m) : 0.f;
        if (tid < HT) s_wh[tid] = __float2half(ex);
        float sm = ex;
        #pragma unroll
        for (int o = 16; o; o >>= 1) sm += __shfl_xor_sync(~0u, sm, o);
        if (lane == 0) s_red[32 + wid] = sm;
        __syncthreads();
        if (tid == 0) {
            float t = 0.f;
            #pragma unroll
            for (int i = 0; i < 16; i++) t += s_red[32 + i];
            s_mS[0] = m; s_mS[1] = t;
        }
        __syncthreads();

        // ---- partial ctx: v[c] = sum_{t half} w[t] * fea[b,c,p*HT+t] ----
        #pragma unroll 1
        for (int cc = 0; cc < 16; cc++) {
            int c = wid * 16 + cc;
            const __half* f = &d_fea_h[((size_t)b * CC + c) * TT + p * HT];
            float acc = 0.f;
            #pragma unroll
            for (int qq = 0; qq < 2; qq++) {
                int t = qq * 256 + lane * 8;
                uint4 fv = *(const uint4*)&f[t];
                uint4 av = *(const uint4*)&s_wh[t];       // 16B/lane: conflict-free
                float fw[8], aw[8];
                h8_to_f(fv, fw);
                h8_to_f(av, aw);
                acc += fw[0]*aw[0] + fw[1]*aw[1] + fw[2]*aw[2] + fw[3]*aw[3]
                     + fw[4]*aw[4] + fw[5]*aw[5] + fw[6]*aw[6] + fw[7]*aw[7];
            }
            #pragma unroll
            for (int o = 16; o; o >>= 1) acc += __shfl_xor_sync(~0u, acc, o);
            if (lane == 0) s_ctx[c] = acc;
        }
        __syncthreads();

        // ---- exchange 1: (v, m, S) via release/acquire ----
        {
            float* buf = &d_xv[par][b][p][0];
            if (tid < HT) buf[tid] = s_ctx[tid];
            if (tid == 0) { buf[512] = s_mS[0]; buf[513] = s_mS[1]; }
            __syncthreads();
            if (tid == 0) {
                sigrel(&d_flag[b][p][0], s + 1);
                while (ldacq(&d_flag[b][q][0]) < s + 1) {}
            }
            __syncthreads();
            const float* pb = &d_xv[par][b][q][0];
            float mpeer = __ldcg(&pb[512]), Speer = __ldcg(&pb[513]);
            float mloc = s_mS[0], Sloc = s_mS[1];
            float m0 = p ? mpeer : mloc, S0 = p ? Speer : Sloc;
            float m1 = p ? mloc : mpeer, S1 = p ? Sloc : Speer;
            float M  = fmaxf(m0, m1);
            float f0 = __expf(m0 - M), f1 = __expf(m1 - M);
            float inv = 1.f / (S0 * f0 + S1 * f1);
            float w0 = f0 * inv, w1 = f1 * inv;
            if (tid < HT) {
                float vpeer = __ldcg(&pb[tid]);
                float v0 = p ? vpeer : s_ctx[tid];
                float v1 = p ? s_ctx[tid] : vpeer;
                s_ctx[tid] = v0 * w0 + v1 * w1;   // identical in both CTAs
            }
        }
        __syncthreads();

        // ---- GRU gemm half: g[n] for n in [p*512, p*512+512), k-split x8 ----
        {
            int kq = tid >> 7, ng = tid & 127, n = p * 512 + ng * 4;
            float acc[4] = {};
            int k0 = kq * 96;
            #pragma unroll 8
            for (int k = k0; k < k0 + 96; k++) {
                int row  = (k < 512) ? k : k + 30;          // skip onehot rows
                float uv = (k < 512) ? s_ctx[k] : s_hid[k - 512];
                uint2 wv = *(const uint2*)&d_wcat_h[(size_t)row * NG + n];
                float2 w0 = __half22float2(((const __half2*)&wv)[0]);
                float2 w1 = __half22float2(((const __half2*)&wv)[1]);
                acc[0] += uv * w0.x; acc[1] += uv * w0.y;
                acc[2] += uv * w1.x; acc[3] += uv * w1.y;
            }
            *(float4*)&s_scr[kq * 512 + ng * 4] = make_float4(acc[0], acc[1], acc[2], acc[3]);
        }
        __syncthreads();
        if (tid < 512) {
            float g = __half2float(d_wcat_h[(size_t)(512 + ch) * NG + p * 512 + tid]);
            #pragma unroll
            for (int kq = 0; kq < 8; kq++) g += s_scr[kq * 512 + tid];
            s_g[p * 512 + tid] = g;
            d_xg[par][b][p][tid] = g;
        }
        __syncthreads();

        // ---- exchange 2: g halves ----
        if (tid == 0) {
            sigrel(&d_flag[b][p][1], s + 1);
            while (ldacq(&d_flag[b][q][1]) < s + 1) {}
        }
        __syncthreads();
        if (tid < 512) s_g[q * 512 + tid] = __ldcg(&d_xg[par][b][q][tid]);
        __syncthreads();

        // ---- gates (redundant in both CTAs -> identical s_hid) ----
        if (tid < HH) {
            int h = tid;
            float gr  = s_g[h]       + b_ih[h]       + b_hh[h];
            float gz  = s_g[256 + h] + b_ih[256 + h] + b_hh[256 + h];
            float ghn = s_g[768 + h] + b_hh[512 + h];
            float gxn = (s_g[512 + h] - s_g[768 + h]) + b_ih[512 + h];
            float r = 1.f / (1.f + expf(-gr));
            float z = 1.f / (1.f + expf(-gz));
            float n = tanhf(gxn + r * ghn);
            s_hid[h] = (1.f - z) * n + z * s_hid[h];
        }
        __syncthreads();

        // ---- heads: (sg1|lg1) matvec + h2h matvec, k-split x8 ----
        {
            int mm = tid >> 9, idx = tid & 511, kq = idx >> 6, hg = idx & 63;
            const __half* w = (mm == 0) ? w_g1 : w_h2h;
            float a[4] = {};
            int k0 = kq * 32;
            #pragma unroll 4
            for (int k = k0; k < k0 + 32; k++) {
                float hv = s_hid[k];
                uint2 wv = *(const uint2*)&w[k * HH + hg * 4];
                float2 w0 = __half22float2(((const __half2*)&wv)[0]);
                float2 w1 = __half22float2(((const __half2*)&wv)[1]);
                a[0] += hv * w0.x; a[1] += hv * w0.y;
                a[2] += hv * w1.x; a[3] += hv * w1.y;
            }
            *(float4*)&s_scr[mm * 2048 + kq * 256 + hg * 4] = make_float4(a[0], a[1], a[2], a[3]);
        }
        __syncthreads();
        if (tid < 512) {
            int mm = tid >> 8, h = tid & 255;
            float v = 0.f;
            #pragma unroll
            for (int kq = 0; kq < 8; kq++) v += s_scr[mm * 2048 + kq * 256 + h];
            if (mm == 0) s_s1[h] = v + b_g1[h];
            else         s_ph[h] = v + h2h_b[h];    // redundant in both CTAs
        }
        __syncthreads();

        // ---- output heads: 16 threads per output element ----
        if (p == 0) {
            if (tid < 16 * NE) {
                int g = tid >> 4, l = tid & 15;
                float sv = 0.f;
                #pragma unroll
                for (int j = 0; j < 16; j++) {
                    int k = l + j * 16;
                    sv += s_s1[k] * sg2_w[k * NE + g];
                }
                #pragma unroll
                for (int o = 8; o; o >>= 1) sv += __shfl_xor_sync(~0u, sv, o);
                if (l == 0) out[((size_t)b * STEPS + s) * NE + g] = sv + sg2_b[g];
            }
        } else {
            if (tid < 64) {
                int g = tid >> 4, l = tid & 15;
                float lv = 0.f;
                #pragma unroll
                for (int j = 0; j < 16; j++) {
                    int k = l + j * 16;
                    lv += s_s1[k] * lg2_w[k * 4 + g];
                }
                #pragma unroll
                for (int o = 8; o; o >>= 1) lv += __shfl_xor_sync(~0u, lv, o);
                if (l == 0)
                    out[(size_t)BB * STEPS * NE + ((size_t)b * STEPS + s) * 4 + g] =
                        1.f / (1.f + expf(-(lv + lg2_b[g])));
            }
        }
        __syncthreads();
    }
}

// ---------------- launch ----------------
extern "C" void kernel_launch(void* const* d_in, const int* in_sizes, int n_in,
                              void* d_out, int out_size) {
    const float* fea      = (const float*)d_in[0];
    const int*   targets  = (const int*)  d_in[1];
    const float* i2h_w    = (const float*)d_in[2];
    const float* h2h_w    = (const float*)d_in[3];
    const float* h2h_b    = (const float*)d_in[4];
    const float* score_w  = (const float*)d_in[5];
    const float* gru_w_ih = (const float*)d_in[6];
    const float* gru_w_hh = (const float*)d_in[7];
    const float* gru_b_ih = (const float*)d_in[8];
    const float* gru_b_hh = (const float*)d_in[9];
    const float* sg1_w    = (const float*)d_in[10];
    const float* sg1_b    = (const float*)d_in[11];
    const float* sg2_w    = (const float*)d_in[12];
    const float* sg2_b    = (const float*)d_in[13];
    const float* lg1_w    = (const float*)d_in[14];
    const float* lg1_b    = (const float*)d_in[15];
    const float* lg2_w    = (const float*)d_in[16];
    const float* lg2_b    = (const float*)d_in[17];
    float* out = (float*)d_out;

    int setup_elems = WROWS * NG + 3 * HH * HH;
    k_setup<<<(setup_elems + 255) / 256, 256>>>(gru_w_ih, gru_w_hh, sg1_w, lg1_w, h2h_w);
    k_conv<<<(int)(((size_t)BB * CC * TT / 4 + 255) / 256), 256>>>(fea);
    k_proj<<<dim3(TT / 64, HH / 64, BB), 256>>>(fea, i2h_w);
    k_decode<<<BB * 2, 1024>>>(targets, score_w,
                               gru_b_ih, gru_b_hh,
                               sg1_b, sg2_w, sg2_b,
                               lg1_b, lg2_w, lg2_b,
                               h2h_b, out);
}

// round 16
// speedup vs baseline: 1.6028x; 1.1348x over previous
#include <cuda_runtime.h>
#include <cuda_fp16.h>
#include <cstdint>

#define BB 64
#define TT 1024
#define CC 512
#define HH 256
#define NE 30
#define STEPS 501
#define NG 1024          // gemm output cols: 768 gates + 256 gh_n
#define WROWS 800        // wcat rows: 512 ctx + 30 onehot + 256 hidden + 2 pad
#define HT 512           // T half per CTA

// ---------------- static scratch (no allocation) ----------------
__device__ __align__(16) __half d_proj_h[(size_t)BB * TT * HH];  // 32 MB
__device__ __align__(16) __half d_fea_h[(size_t)BB * CC * TT];   // 64 MB
__device__ __align__(16) __half d_wcat_h[WROWS * NG];            // 1.6 MB
__device__ __align__(16) __half d_hw_h[3 * HH * HH];             // sg1 | lg1 | h2h
// cross-CTA exchange (parity double-buffered) + flags
__device__ __align__(16) float d_xv[2][BB][2][516];              // ctx partial[512] + S
__device__ __align__(16) float d_xg[2][BB][2][512];              // gemm halves
__device__ int d_flag[BB][2][2];                                 // [b][p][phase]

__device__ __forceinline__ void h8_to_f(uint4 v, float* f) {
    const __half2* p = (const __half2*)&v;
    #pragma unroll
    for (int i = 0; i < 4; i++) { float2 t = __half22float2(p[i]); f[2*i] = t.x; f[2*i+1] = t.y; }
}
// release-store / acquire-load flag ops (no CCTL.IVALL, unlike __threadfence)
__device__ __forceinline__ void sigrel(int* p, int v) {
    asm volatile("st.release.gpu.global.b32 [%0], %1;" :: "l"(p), "r"(v) : "memory");
}
__device__ __forceinline__ int ldacq(const int* p) {
    int v; asm volatile("ld.acquire.gpu.global.b32 %0, [%1];" : "=r"(v) : "l"(p) : "memory");
    return v;
}

// ---------------- setup: fp16 Wcat + head weights + flag reset ----------------
__global__ void k_setup(const float* __restrict__ w_ih, const float* __restrict__ w_hh,
                        const float* __restrict__ sg1_w, const float* __restrict__ lg1_w,
                        const float* __restrict__ h2h_w) {
    int idx = blockIdx.x * 256 + threadIdx.x;
    if (idx < BB * 2 * 2) ((int*)d_flag)[idx] = 0;
    if (idx < WROWS * NG) {
        int k = idx >> 10, j = idx & 1023;
        float v = 0.f;
        if (j < 768) {
            if (k < 542)      v = w_ih[k * 768 + j];
            else if (k < 798) v = w_hh[(k - 542) * 768 + j];
        } else {
            if (k >= 542 && k < 798) v = w_hh[(k - 542) * 768 + 512 + (j - 768)];
        }
        d_wcat_h[idx] = __float2half(v);
    }
    int idx2 = idx - WROWS * NG;
    if (idx2 >= 0 && idx2 < 3 * HH * HH) {
        int mm = idx2 >> 16, i = idx2 & 65535;
        const float* w = (mm == 0) ? sg1_w : (mm == 1) ? lg1_w : h2h_w;
        d_hw_h[idx2] = __float2half(w[i]);
    }
}

// ---------------- fea -> fp16 ----------------
__global__ __launch_bounds__(256) void k_conv(const float* __restrict__ fea) {
    size_t i = ((size_t)blockIdx.x * 256 + threadIdx.x) * 4;
    if (i >= (size_t)BB * CC * TT) return;
    float4 v = *(const float4*)&fea[i];
    *(__half2*)&d_fea_h[i]     = __floats2half2_rn(v.x, v.y);
    *(__half2*)&d_fea_h[i + 2] = __floats2half2_rn(v.z, v.w);
}

// ---------------- proj[b,t,h] = sum_c fea[b,c,t] * i2h_w[c,h] ----------------
__global__ __launch_bounds__(256) void k_proj(const float* __restrict__ fea,
                                              const float* __restrict__ i2h_w) {
    int t0 = blockIdx.x * 64, h0 = blockIdx.y * 64, b = blockIdx.z;
    __shared__ float As[8][64];
    __shared__ float Bs[8][64];
    int tid = threadIdx.x;
    int tx = tid & 15, ty = tid >> 4;
    float acc[4][4] = {};
    for (int k0 = 0; k0 < CC; k0 += 8) {
        #pragma unroll
        for (int r = 0; r < 2; r++) {
            int i = tid + r * 256;
            int kk = i >> 6, m = i & 63;
            As[kk][m] = fea[((size_t)b * CC + (k0 + kk)) * TT + t0 + m];
            Bs[kk][m] = i2h_w[(k0 + kk) * HH + h0 + m];
        }
        __syncthreads();
        #pragma unroll
        for (int kk = 0; kk < 8; kk++) {
            float a[4], bv[4];
            #pragma unroll
            for (int i = 0; i < 4; i++) a[i] = As[kk][ty * 4 + i];
            #pragma unroll
            for (int j = 0; j < 4; j++) bv[j] = Bs[kk][tx * 4 + j];
            #pragma unroll
            for (int i = 0; i < 4; i++)
                #pragma unroll
                for (int j = 0; j < 4; j++) acc[i][j] += a[i] * bv[j];
        }
        __syncthreads();
    }
    #pragma unroll
    for (int i = 0; i < 4; i++) {
        size_t base = ((size_t)b * TT + t0 + ty * 4 + i) * HH + h0 + tx * 4;
        *(__half2*)&d_proj_h[base]     = __floats2half2_rn(acc[i][0], acc[i][1]);
        *(__half2*)&d_proj_h[base + 2] = __floats2half2_rn(acc[i][2], acc[i][3]);
    }
}

// ---------------- decode: 2 CTAs per batch (T-split + col-split) ----------------
__global__ __launch_bounds__(1024, 1) void k_decode(
    const int* __restrict__ targets,
    const float* __restrict__ score_w,
    const float* __restrict__ b_ih, const float* __restrict__ b_hh,
    const float* __restrict__ sg1_b, const float* __restrict__ sg2_w,
    const float* __restrict__ sg2_b, const float* __restrict__ lg1_b,
    const float* __restrict__ lg2_w, const float* __restrict__ lg2_b,
    const float* __restrict__ h2h_b,
    float* __restrict__ out)
{
    __shared__ __align__(16) __half s_wh[HT];     // unnormalized exp weights (fp16, m=0)
    __shared__ __align__(16) float  s_ctx[CC];
    __shared__ __align__(16) float  s_hid[HH];
    __shared__ __align__(16) float  s_ph[HH];
    __shared__ __align__(16) float  s_g[NG];
    __shared__ __align__(16) float  s_scr[4096];  // 16 KB partials (gemm / heads)
    __shared__ __align__(16) float  s_s1[HH];
    __shared__ float s_red[32];
    __shared__ float s_mS[2];                     // [0]=S local, [1]=S peer

    int b = blockIdx.x >> 1, p = blockIdx.x & 1, q = 1 - p;
    int tid = threadIdx.x, wid = tid >> 5, lane = tid & 31;
    const __half* w_g1  = d_hw_h + (size_t)p * HH * HH;       // sg1 (p=0) / lg1 (p=1)
    const __half* w_h2h = d_hw_h + (size_t)2 * HH * HH;
    const float*  b_g1  = p ? lg1_b : sg1_b;

    if (tid < HH) { s_hid[tid] = 0.f; s_ph[tid] = h2h_b[tid]; }   // h0=0 -> ph=bias
    float rsw[8];
    #pragma unroll
    for (int i = 0; i < 8; i++) rsw[i] = score_w[lane * 8 + i];
    __syncthreads();

    for (int s = 0; s < STEPS; s++) {
        int ch = targets[b * STEPS + s];
        int par = s & 1;
        __half2 rph2[4];
        #pragma unroll
        for (int i = 0; i < 4; i++)
            rph2[i] = __floats2half2_rn(s_ph[lane * 8 + 2*i], s_ph[lane * 8 + 2*i + 1]);

        // ---- scores + exp (m=0, |e|<=10.2 a-priori) + per-warp S partials ----
        const uint4* pbase =
            (const uint4*)&d_proj_h[((size_t)b * TT + p * HT + wid * 16) * HH + lane * 8];
        float sacc = 0.f;
        #pragma unroll 4
        for (int tt = 0; tt < 16; tt++) {
            uint4 pv = pbase[(size_t)tt * (HH / 8)];
            const __half2* ph2 = (const __half2*)&pv;
            float a = 0.f;
            #pragma unroll
            for (int i = 0; i < 4; i++) {
                __half2 x = __hadd2(ph2[i], rph2[i]);
                unsigned xr = *(unsigned*)&x, th;
                asm("tanh.approx.f16x2 %0, %1;" : "=r"(th) : "r"(xr));
                float2 tf = __half22float2(*(__half2*)&th);
                a += tf.x * rsw[2*i] + tf.y * rsw[2*i + 1];
            }
            #pragma unroll
            for (int o = 16; o; o >>= 1) a += __shfl_xor_sync(~0u, a, o);
            if (lane == 0) {
                float ex = __expf(fminf(a, 11.f));    // clamp never fires: |e|<=sum|sw|<11
                s_wh[wid * 16 + tt] = __float2half(ex);
                sacc += ex;
            }
        }
        if (lane == 0) s_red[wid] = sacc;
        __syncthreads();

        // ---- partial ctx: v[c] = sum_{t half} w[t]*fea; lane0 also STGs to buf ----
        float* buf = &d_xv[par][b][p][0];
        #pragma unroll 1
        for (int cc = 0; cc < 16; cc++) {
            int c = wid * 16 + cc;
            const __half* f = &d_fea_h[((size_t)b * CC + c) * TT + p * HT];
            float acc = 0.f;
            #pragma unroll
            for (int qq = 0; qq < 2; qq++) {
                int t = qq * 256 + lane * 8;
                uint4 fv = *(const uint4*)&f[t];
                uint4 av = *(const uint4*)&s_wh[t];       // 16B/lane: conflict-free
                float fw[8], aw[8];
                h8_to_f(fv, fw);
                h8_to_f(av, aw);
                acc += fw[0]*aw[0] + fw[1]*aw[1] + fw[2]*aw[2] + fw[3]*aw[3]
                     + fw[4]*aw[4] + fw[5]*aw[5] + fw[6]*aw[6] + fw[7]*aw[7];
            }
            #pragma unroll
            for (int o = 16; o; o >>= 1) acc += __shfl_xor_sync(~0u, acc, o);
            if (lane == 0) { s_ctx[c] = acc; buf[c] = acc; }
        }
        if (tid == 0) {
            float S = 0.f;
            #pragma unroll
            for (int i = 0; i < 32; i++) S += s_red[i];
            s_mS[0] = S;
            buf[512] = S;
        }
        __syncthreads();
        if (tid == 0) sigrel(&d_flag[b][p][0], s + 1);   // post; wait AFTER hidden gemm

        // ---- GRU gemm phase A: hidden rows (peer-independent), k-split x8 ----
        {
            int kq = tid >> 7, ng = tid & 127, n = p * 512 + ng * 4;
            float acc[4] = {};
            int k0 = 512 + kq * 32;
            #pragma unroll 8
            for (int k = k0; k < k0 + 32; k++) {
                float uv = s_hid[k - 512];
                uint2 wv = *(const uint2*)&d_wcat_h[(size_t)(k + 30) * NG + n];
                float2 w0 = __half22float2(((const __half2*)&wv)[0]);
                float2 w1 = __half22float2(((const __half2*)&wv)[1]);
                acc[0] += uv * w0.x; acc[1] += uv * w0.y;
                acc[2] += uv * w1.x; acc[3] += uv * w1.y;
            }
            *(float4*)&s_scr[kq * 512 + ng * 4] = make_float4(acc[0], acc[1], acc[2], acc[3]);
        }
        // ---- now wait for peer ctx, pull S ----
        if (tid == 0) {
            while (ldacq(&d_flag[b][q][0]) < s + 1) {}
            s_mS[1] = __ldcg(&d_xv[par][b][q][512]);
        }
        __syncthreads();

        // ---- combine ctx: (v_local + v_peer) / (S_local + S_peer) ----
        {
            float inv = 1.f / (s_mS[0] + s_mS[1]);
            if (tid < HT)
                s_ctx[tid] = (s_ctx[tid] + __ldcg(&d_xv[par][b][q][tid])) * inv;
        }
        __syncthreads();

        // ---- GRU gemm phase B: ctx rows, accumulate onto phase-A partials ----
        {
            int kq = tid >> 7, ng = tid & 127, n = p * 512 + ng * 4;
            float acc[4] = {};
            int k0 = kq * 64;
            #pragma unroll 8
            for (int k = k0; k < k0 + 64; k++) {
                float uv = s_ctx[k];
                uint2 wv = *(const uint2*)&d_wcat_h[(size_t)k * NG + n];
                float2 w0 = __half22float2(((const __half2*)&wv)[0]);
                float2 w1 = __half22float2(((const __half2*)&wv)[1]);
                acc[0] += uv * w0.x; acc[1] += uv * w0.y;
                acc[2] += uv * w1.x; acc[3] += uv * w1.y;
            }
            float4* dst = (float4*)&s_scr[kq * 512 + ng * 4];
            float4 o = *dst;
            *dst = make_float4(o.x + acc[0], o.y + acc[1], o.z + acc[2], o.w + acc[3]);
        }
        __syncthreads();
        if (tid < 512) {
            float g = __half2float(d_wcat_h[(size_t)(512 + ch) * NG + p * 512 + tid]);
            #pragma unroll
            for (int kq = 0; kq < 8; kq++) g += s_scr[kq * 512 + tid];
            s_g[p * 512 + tid] = g;
            d_xg[par][b][p][tid] = g;
        }
        __syncthreads();

        // ---- exchange 2: g halves ----
        if (tid == 0) {
            sigrel(&d_flag[b][p][1], s + 1);
            while (ldacq(&d_flag[b][q][1]) < s + 1) {}
        }
        __syncthreads();
        if (tid < 512) s_g[q * 512 + tid] = __ldcg(&d_xg[par][b][q][tid]);
        __syncthreads();

        // ---- gates (redundant in both CTAs -> identical s_hid) ----
        if (tid < HH) {
            int h = tid;
            float gr  = s_g[h]       + b_ih[h]       + b_hh[h];
            float gz  = s_g[256 + h] + b_ih[256 + h] + b_hh[256 + h];
            float ghn = s_g[768 + h] + b_hh[512 + h];
            float gxn = (s_g[512 + h] - s_g[768 + h]) + b_ih[512 + h];
            float r = 1.f / (1.f + expf(-gr));
            float z = 1.f / (1.f + expf(-gz));
            float n = tanhf(gxn + r * ghn);
            s_hid[h] = (1.f - z) * n + z * s_hid[h];
        }
        __syncthreads();

        // ---- heads: (sg1|lg1) matvec + h2h matvec, k-split x8 ----
        {
            int mm = tid >> 9, idx = tid & 511, kq = idx >> 6, hg = idx & 63;
            const __half* w = (mm == 0) ? w_g1 : w_h2h;
            float a[4] = {};
            int k0 = kq * 32;
            #pragma unroll 4
            for (int k = k0; k < k0 + 32; k++) {
                float hv = s_hid[k];
                uint2 wv = *(const uint2*)&w[k * HH + hg * 4];
                float2 w0 = __half22float2(((const __half2*)&wv)[0]);
                float2 w1 = __half22float2(((const __half2*)&wv)[1]);
                a[0] += hv * w0.x; a[1] += hv * w0.y;
                a[2] += hv * w1.x; a[3] += hv * w1.y;
            }
            *(float4*)&s_scr[mm * 2048 + kq * 256 + hg * 4] = make_float4(a[0], a[1], a[2], a[3]);
        }
        __syncthreads();
        if (tid < 512) {
            int mm = tid >> 8, h = tid & 255;
            float v = 0.f;
            #pragma unroll
            for (int kq = 0; kq < 8; kq++) v += s_scr[mm * 2048 + kq * 256 + h];
            if (mm == 0) s_s1[h] = v + b_g1[h];
            else         s_ph[h] = v + h2h_b[h];    // redundant in both CTAs
        }
        __syncthreads();

        // ---- output heads: 16 threads per output element ----
        if (p == 0) {
            if (tid < 16 * NE) {
                int g = tid >> 4, l = tid & 15;
                float sv = 0.f;
                #pragma unroll
                for (int j = 0; j < 16; j++) {
                    int k = l + j * 16;
                    sv += s_s1[k] * sg2_w[k * NE + g];
                }
                #pragma unroll
                for (int o = 8; o; o >>= 1) sv += __shfl_xor_sync(~0u, sv, o);
                if (l == 0) out[((size_t)b * STEPS + s) * NE + g] = sv + sg2_b[g];
            }
        } else {
            if (tid < 64) {
                int g = tid >> 4, l = tid & 15;
                float lv = 0.f;
                #pragma unroll
                for (int j = 0; j < 16; j++) {
                    int k = l + j * 16;
                    lv += s_s1[k] * lg2_w[k * 4 + g];
                }
                #pragma unroll
                for (int o = 8; o; o >>= 1) lv += __shfl_xor_sync(~0u, lv, o);
                if (l == 0)
                    out[(size_t)BB * STEPS * NE + ((size_t)b * STEPS + s) * 4 + g] =
                        1.f / (1.f + expf(-(lv + lg2_b[g])));
            }
        }
        __syncthreads();
    }
}

// ---------------- launch ----------------
extern "C" void kernel_launch(void* const* d_in, const int* in_sizes, int n_in,
                              void* d_out, int out_size) {
    const float* fea      = (const float*)d_in[0];
    const int*   targets  = (const int*)  d_in[1];
    const float* i2h_w    = (const float*)d_in[2];
    const float* h2h_w    = (const float*)d_in[3];
    const float* h2h_b    = (const float*)d_in[4];
    const float* score_w  = (const float*)d_in[5];
    const float* gru_w_ih = (const float*)d_in[6];
    const float* gru_w_hh = (const float*)d_in[7];
    const float* gru_b_ih = (const float*)d_in[8];
    const float* gru_b_hh = (const float*)d_in[9];
    const float* sg1_w    = (const float*)d_in[10];
    const float* sg1_b    = (const float*)d_in[11];
    const float* sg2_w    = (const float*)d_in[12];
    const float* sg2_b    = (const float*)d_in[13];
    const float* lg1_w    = (const float*)d_in[14];
    const float* lg1_b    = (const float*)d_in[15];
    const float* lg2_w    = (const float*)d_in[16];
    const float* lg2_b    = (const float*)d_in[17];
    float* out = (float*)d_out;

    int setup_elems = WROWS * NG + 3 * HH * HH;
    k_setup<<<(setup_elems + 255) / 256, 256>>>(gru_w_ih, gru_w_hh, sg1_w, lg1_w, h2h_w);
    k_conv<<<(int)(((size_t)BB * CC * TT / 4 + 255) / 256), 256>>>(fea);
    k_proj<<<dim3(TT / 64, HH / 64, BB), 256>>>(fea, i2h_w);
    k_decode<<<BB * 2, 1024>>>(targets, score_w,
                               gru_b_ih, gru_b_hh,
                               sg1_b, sg2_w, sg2_b,
                               lg1_b, lg2_w, lg2_b,
                               h2h_b, out);
}

// round 17
// speedup vs baseline: 1.6119x; 1.0057x over previous
#include <cuda_runtime.h>
#include <cuda_fp16.h>
#include <cstdint>

#define BB 64
#define TT 1024
#define CC 512
#define HH 256
#define NE 30
#define STEPS 501
#define NG 1024          // gemm output cols: 768 gates + 256 gh_n
#define WROWS 800        // wcat rows: 512 ctx + 30 onehot + 256 hidden + 2 pad
#define HT 512           // T half per CTA

// ---------------- static scratch (no allocation) ----------------
__device__ __align__(16) __half d_proj_h[(size_t)BB * TT * HH];  // 32 MB
__device__ __align__(16) __half d_fea_h[(size_t)BB * CC * TT];   // 64 MB
__device__ __align__(16) __half d_wcat_h[WROWS * NG];            // 1.6 MB
__device__ __align__(16) __half d_hw_h[3 * HH * HH];             // sg1 | lg1 | h2h
// cross-CTA exchange (parity double-buffered) + flags
__device__ __align__(16) float d_xv[2][BB][2][516];              // ctx partial[512] + S
__device__ __align__(16) float d_xh[2][BB][2][128];              // new-hidden halves
__device__ int d_flag[BB][2][2];                                 // [b][p][phase]

__device__ __forceinline__ void h8_to_f(uint4 v, float* f) {
    const __half2* p = (const __half2*)&v;
    #pragma unroll
    for (int i = 0; i < 4; i++) { float2 t = __half22float2(p[i]); f[2*i] = t.x; f[2*i+1] = t.y; }
}
// release-store / acquire-load flag ops (no CCTL.IVALL, unlike __threadfence)
__device__ __forceinline__ void sigrel(int* p, int v) {
    asm volatile("st.release.gpu.global.b32 [%0], %1;" :: "l"(p), "r"(v) : "memory");
}
__device__ __forceinline__ int ldacq(const int* p) {
    int v; asm volatile("ld.acquire.gpu.global.b32 %0, [%1];" : "=r"(v) : "l"(p) : "memory");
    return v;
}

// ---------------- setup: fp16 Wcat + head weights + flag reset ----------------
__global__ void k_setup(const float* __restrict__ w_ih, const float* __restrict__ w_hh,
                        const float* __restrict__ sg1_w, const float* __restrict__ lg1_w,
                        const float* __restrict__ h2h_w) {
    int idx = blockIdx.x * 256 + threadIdx.x;
    if (idx < BB * 2 * 2) ((int*)d_flag)[idx] = 0;
    if (idx < WROWS * NG) {
        int k = idx >> 10, j = idx & 1023;
        float v = 0.f;
        if (j < 768) {
            if (k < 542)      v = w_ih[k * 768 + j];
            else if (k < 798) v = w_hh[(k - 542) * 768 + j];
        } else {
            if (k >= 542 && k < 798) v = w_hh[(k - 542) * 768 + 512 + (j - 768)];
        }
        d_wcat_h[idx] = __float2half(v);
    }
    int idx2 = idx - WROWS * NG;
    if (idx2 >= 0 && idx2 < 3 * HH * HH) {
        int mm = idx2 >> 16, i = idx2 & 65535;
        const float* w = (mm == 0) ? sg1_w : (mm == 1) ? lg1_w : h2h_w;
        d_hw_h[idx2] = __float2half(w[i]);
    }
}

// ---------------- fea -> fp16 ----------------
__global__ __launch_bounds__(256) void k_conv(const float* __restrict__ fea) {
    size_t i = ((size_t)blockIdx.x * 256 + threadIdx.x) * 4;
    if (i >= (size_t)BB * CC * TT) return;
    float4 v = *(const float4*)&fea[i];
    *(__half2*)&d_fea_h[i]     = __floats2half2_rn(v.x, v.y);
    *(__half2*)&d_fea_h[i + 2] = __floats2half2_rn(v.z, v.w);
}

// ---------------- proj[b,t,h] = sum_c fea[b,c,t] * i2h_w[c,h] ----------------
__global__ __launch_bounds__(256) void k_proj(const float* __restrict__ fea,
                                              const float* __restrict__ i2h_w) {
    int t0 = blockIdx.x * 64, h0 = blockIdx.y * 64, b = blockIdx.z;
    __shared__ float As[8][64];
    __shared__ float Bs[8][64];
    int tid = threadIdx.x;
    int tx = tid & 15, ty = tid >> 4;
    float acc[4][4] = {};
    for (int k0 = 0; k0 < CC; k0 += 8) {
        #pragma unroll
        for (int r = 0; r < 2; r++) {
            int i = tid + r * 256;
            int kk = i >> 6, m = i & 63;
            As[kk][m] = fea[((size_t)b * CC + (k0 + kk)) * TT + t0 + m];
            Bs[kk][m] = i2h_w[(k0 + kk) * HH + h0 + m];
        }
        __syncthreads();
        #pragma unroll
        for (int kk = 0; kk < 8; kk++) {
            float a[4], bv[4];
            #pragma unroll
            for (int i = 0; i < 4; i++) a[i] = As[kk][ty * 4 + i];
            #pragma unroll
            for (int j = 0; j < 4; j++) bv[j] = Bs[kk][tx * 4 + j];
            #pragma unroll
            for (int i = 0; i < 4; i++)
                #pragma unroll
                for (int j = 0; j < 4; j++) acc[i][j] += a[i] * bv[j];
        }
        __syncthreads();
    }
    #pragma unroll
    for (int i = 0; i < 4; i++) {
        size_t base = ((size_t)b * TT + t0 + ty * 4 + i) * HH + h0 + tx * 4;
        *(__half2*)&d_proj_h[base]     = __floats2half2_rn(acc[i][0], acc[i][1]);
        *(__half2*)&d_proj_h[base + 2] = __floats2half2_rn(acc[i][2], acc[i][3]);
    }
}

// ---------------- decode: 2 CTAs per batch (T-split + interleaved col-split) ----------------
__global__ __launch_bounds__(1024, 1) void k_decode(
    const int* __restrict__ targets,
    const float* __restrict__ score_w,
    const float* __restrict__ b_ih, const float* __restrict__ b_hh,
    const float* __restrict__ sg1_b, const float* __restrict__ sg2_w,
    const float* __restrict__ sg2_b, const float* __restrict__ lg1_b,
    const float* __restrict__ lg2_w, const float* __restrict__ lg2_b,
    const float* __restrict__ h2h_b,
    float* __restrict__ out)
{
    __shared__ __align__(16) float  s_wf[HT];     // unnormalized exp weights (f32, m=0)
    __shared__ __align__(16) float  s_ctx[CC];
    __shared__ __align__(16) float  s_hid[HH];
    __shared__ __align__(16) float  s_ph[HH];
    __shared__ __align__(16) float  s_scr[4096];  // 16 KB partials (gemm / heads)
    __shared__ __align__(16) float  s_s1[HH];
    __shared__ float s_red[32];
    __shared__ float s_mS[1];                     // S local

    int b = blockIdx.x >> 1, p = blockIdx.x & 1, q = 1 - p;
    int tid = threadIdx.x, wid = tid >> 5, lane = tid & 31;
    const __half* w_g1  = d_hw_h + (size_t)p * HH * HH;       // sg1 (p=0) / lg1 (p=1)
    const __half* w_h2h = d_hw_h + (size_t)2 * HH * HH;
    const float*  b_g1  = p ? lg1_b : sg1_b;

    if (tid < HH) { s_hid[tid] = 0.f; s_ph[tid] = h2h_b[tid]; }   // h0=0 -> ph=bias
    float rsw[8];
    #pragma unroll
    for (int i = 0; i < 8; i++) rsw[i] = score_w[lane * 8 + i];
    __syncthreads();

    for (int s = 0; s < STEPS; s++) {
        int ch = targets[b * STEPS + s];
        int par = s & 1;
        __half2 rph2[4];
        #pragma unroll
        for (int i = 0; i < 4; i++)
            rph2[i] = __floats2half2_rn(s_ph[lane * 8 + 2*i], s_ph[lane * 8 + 2*i + 1]);

        // ---- scores + exp (m=0, |e|<=10.2 a-priori) + per-warp S partials ----
        const uint4* pbase =
            (const uint4*)&d_proj_h[((size_t)b * TT + p * HT + wid * 16) * HH + lane * 8];
        float sacc = 0.f;
        #pragma unroll 4
        for (int tt = 0; tt < 16; tt++) {
            uint4 pv = pbase[(size_t)tt * (HH / 8)];
            const __half2* ph2 = (const __half2*)&pv;
            float a = 0.f;
            #pragma unroll
            for (int i = 0; i < 4; i++) {
                __half2 x = __hadd2(ph2[i], rph2[i]);
                unsigned xr = *(unsigned*)&x, th;
                asm("tanh.approx.f16x2 %0, %1;" : "=r"(th) : "r"(xr));
                float2 tf = __half22float2(*(__half2*)&th);
                a += tf.x * rsw[2*i] + tf.y * rsw[2*i + 1];
            }
            #pragma unroll
            for (int o = 16; o; o >>= 1) a += __shfl_xor_sync(~0u, a, o);
            if (lane == 0) {
                float ex = __expf(fminf(a, 11.f));    // clamp never fires: |e|<=sum|sw|<11
                s_wf[wid * 16 + tt] = ex;
                sacc += ex;
            }
        }
        if (lane == 0) s_red[wid] = sacc;
        __syncthreads();                                         // B1

        // ---- partial ctx: v[c] = sum_{t half} w[t]*fea; lane0 also STGs to buf ----
        float* buf = &d_xv[par][b][p][0];
        #pragma unroll 1
        for (int cc = 0; cc < 16; cc++) {
            int c = wid * 16 + cc;
            const __half* f = &d_fea_h[((size_t)b * CC + c) * TT + p * HT];
            float acc = 0.f;
            #pragma unroll
            for (int qq = 0; qq < 2; qq++) {
                int t = qq * 256 + lane * 8;
                uint4 fv = *(const uint4*)&f[t];
                float4 a0 = *(const float4*)&s_wf[t];
                float4 a1 = *(const float4*)&s_wf[t + 4];
                float fw[8]; h8_to_f(fv, fw);
                acc += fw[0]*a0.x + fw[1]*a0.y + fw[2]*a0.z + fw[3]*a0.w
                     + fw[4]*a1.x + fw[5]*a1.y + fw[6]*a1.z + fw[7]*a1.w;
            }
            #pragma unroll
            for (int o = 16; o; o >>= 1) acc += __shfl_xor_sync(~0u, acc, o);
            if (lane == 0) { s_ctx[c] = acc; buf[c] = acc; }
        }
        if (tid == 0) {
            float S = 0.f;
            #pragma unroll
            for (int i = 0; i < 32; i++) S += s_red[i];
            s_mS[0] = S;
            buf[512] = S;
        }
        __syncthreads();                                         // B2
        if (tid == 0) sigrel(&d_flag[b][p][0], s + 1);   // post; wait AFTER hidden gemm

        // ---- GRU gemm phase A: hidden rows (peer-independent), interleaved cols ----
        {
            int kq = tid >> 7, lc = tid & 127;
            int n = ((lc >> 5) << 8) + p * 128 + ((lc & 31) << 2);
            float acc[4] = {};
            int k0 = 512 + kq * 32;
            #pragma unroll 8
            for (int k = k0; k < k0 + 32; k++) {
                float uv = s_hid[k - 512];
                uint2 wv = *(const uint2*)&d_wcat_h[(size_t)(k + 30) * NG + n];
                float2 w0 = __half22float2(((const __half2*)&wv)[0]);
                float2 w1 = __half22float2(((const __half2*)&wv)[1]);
                acc[0] += uv * w0.x; acc[1] += uv * w0.y;
                acc[2] += uv * w1.x; acc[3] += uv * w1.y;
            }
            *(float4*)&s_scr[kq * 512 + lc * 4] = make_float4(acc[0], acc[1], acc[2], acc[3]);
        }
        // ---- combine ctx: per-thread poll, (v_local+v_peer)/(S_local+S_peer) ----
        if (tid < HT) {
            while (ldacq(&d_flag[b][q][0]) < s + 1) {}
            float Sp  = __ldcg(&d_xv[par][b][q][512]);
            float inv = 1.f / (s_mS[0] + Sp);
            s_ctx[tid] = (s_ctx[tid] + __ldcg(&d_xv[par][b][q][tid])) * inv;
        }
        __syncthreads();                                         // B3

        // ---- GRU gemm phase B: ctx rows, accumulate onto phase-A partials ----
        {
            int kq = tid >> 7, lc = tid & 127;
            int n = ((lc >> 5) << 8) + p * 128 + ((lc & 31) << 2);
            float acc[4] = {};
            int k0 = kq * 64;
            #pragma unroll 8
            for (int k = k0; k < k0 + 64; k++) {
                float uv = s_ctx[k];
                uint2 wv = *(const uint2*)&d_wcat_h[(size_t)k * NG + n];
                float2 w0 = __half22float2(((const __half2*)&wv)[0]);
                float2 w1 = __half22float2(((const __half2*)&wv)[1]);
                acc[0] += uv * w0.x; acc[1] += uv * w0.y;
                acc[2] += uv * w1.x; acc[3] += uv * w1.y;
            }
            float4* dst = (float4*)&s_scr[kq * 512 + lc * 4];
            float4 o = *dst;
            *dst = make_float4(o.x + acc[0], o.y + acc[1], o.z + acc[2], o.w + acc[3]);
        }
        __syncthreads();                                         // B4

        // ---- gates: own 128 h, fused partial-reduction; exchange only h_new ----
        if (tid < 128) {
            int i = tid, h = p * 128 + i;
            float gl[4];
            #pragma unroll
            for (int j = 0; j < 4; j++) {
                int n = j * 256 + p * 128 + i;
                float g = __half2float(d_wcat_h[(size_t)(512 + ch) * NG + n]);  // onehot row
                #pragma unroll
                for (int kq = 0; kq < 8; kq++) g += s_scr[kq * 512 + j * 128 + i];
                gl[j] = g;
            }
            float gr  = gl[0] + b_ih[h]       + b_hh[h];
            float gz  = gl[1] + b_ih[256 + h] + b_hh[256 + h];
            float ghn = gl[3] + b_hh[512 + h];
            float gxn = (gl[2] - gl[3]) + b_ih[512 + h];
            float r = 1.f / (1.f + expf(-gr));
            float z = 1.f / (1.f + expf(-gz));
            float nn = tanhf(gxn + r * ghn);
            float hn = (1.f - z) * nn + z * s_hid[h];
            s_hid[h] = hn;
            d_xh[par][b][p][i] = hn;
        }
        __syncthreads();                                         // B5
        if (tid == 0) sigrel(&d_flag[b][p][1], s + 1);

        // ---- heads phase A: own k-half (overlaps peer h wait) ----
        {
            int mm = tid >> 9, idx = tid & 511, kq = idx >> 6, hg = idx & 63;
            const __half* w = (mm == 0) ? w_g1 : w_h2h;
            float a[4] = {};
            int k0 = p * 128 + kq * 16;
            #pragma unroll 8
            for (int k = k0; k < k0 + 16; k++) {
                float hv = s_hid[k];
                uint2 wv = *(const uint2*)&w[k * HH + hg * 4];
                float2 w0 = __half22float2(((const __half2*)&wv)[0]);
                float2 w1 = __half22float2(((const __half2*)&wv)[1]);
                a[0] += hv * w0.x; a[1] += hv * w0.y;
                a[2] += hv * w1.x; a[3] += hv * w1.y;
            }
            *(float4*)&s_scr[mm * 2048 + kq * 256 + hg * 4] = make_float4(a[0], a[1], a[2], a[3]);
        }
        // ---- pull peer h_new (per-thread poll) ----
        if (tid < 128) {
            while (ldacq(&d_flag[b][q][1]) < s + 1) {}
            s_hid[q * 128 + tid] = __ldcg(&d_xh[par][b][q][tid]);
        }
        __syncthreads();                                         // B6

        // ---- heads phase B: peer k-half, accumulate ----
        {
            int mm = tid >> 9, idx = tid & 511, kq = idx >> 6, hg = idx & 63;
            const __half* w = (mm == 0) ? w_g1 : w_h2h;
            float a[4] = {};
            int k0 = q * 128 + kq * 16;
            #pragma unroll 8
            for (int k = k0; k < k0 + 16; k++) {
                float hv = s_hid[k];
                uint2 wv = *(const uint2*)&w[k * HH + hg * 4];
                float2 w0 = __half22float2(((const __half2*)&wv)[0]);
                float2 w1 = __half22float2(((const __half2*)&wv)[1]);
                a[0] += hv * w0.x; a[1] += hv * w0.y;
                a[2] += hv * w1.x; a[3] += hv * w1.y;
            }
            float4* dst = (float4*)&s_scr[mm * 2048 + kq * 256 + hg * 4];
            float4 o = *dst;
            *dst = make_float4(o.x + a[0], o.y + a[1], o.z + a[2], o.w + a[3]);
        }
        __syncthreads();                                         // B7

        // ---- heads reduce -> s_s1 / s_ph ----
        if (tid < 512) {
            int mm = tid >> 8, h = tid & 255;
            float v = 0.f;
            #pragma unroll
            for (int kq = 0; kq < 8; kq++) v += s_scr[mm * 2048 + kq * 256 + h];
            if (mm == 0) s_s1[h] = v + b_g1[h];
            else         s_ph[h] = v + h2h_b[h];
        }
        __syncthreads();                                         // B8

        // ---- output heads: 16 threads per output element ----
        if (p == 0) {
            if (tid < 16 * NE) {
                int g = tid >> 4, l = tid & 15;
                float sv = 0.f;
                #pragma unroll
                for (int j = 0; j < 16; j++) {
                    int k = l + j * 16;
                    sv += s_s1[k] * sg2_w[k * NE + g];
                }
                #pragma unroll
                for (int o = 8; o; o >>= 1) sv += __shfl_xor_sync(~0u, sv, o);
                if (l == 0) out[((size_t)b * STEPS + s) * NE + g] = sv + sg2_b[g];
            }
        } else {
            if (tid < 64) {
                int g = tid >> 4, l = tid & 15;
                float lv = 0.f;
                #pragma unroll
                for (int j = 0; j < 16; j++) {
                    int k = l + j * 16;
                    lv += s_s1[k] * lg2_w[k * 4 + g];
                }
                #pragma unroll
                for (int o = 8; o; o >>= 1) lv += __shfl_xor_sync(~0u, lv, o);
                if (l == 0)
                    out[(size_t)BB * STEPS * NE + ((size_t)b * STEPS + s) * 4 + g] =
                        1.f / (1.f + expf(-(lv + lg2_b[g])));
            }
        }
        __syncthreads();                                         // B9
    }
}

// ---------------- launch ----------------
extern "C" void kernel_launch(void* const* d_in, const int* in_sizes, int n_in,
                              void* d_out, int out_size) {
    const float* fea      = (const float*)d_in[0];
    const int*   targets  = (const int*)  d_in[1];
    const float* i2h_w    = (const float*)d_in[2];
    const float* h2h_w    = (const float*)d_in[3];
    const float* h2h_b    = (const float*)d_in[4];
    const float* score_w  = (const float*)d_in[5];
    const float* gru_w_ih = (const float*)d_in[6];
    const float* gru_w_hh = (const float*)d_in[7];
    const float* gru_b_ih = (const float*)d_in[8];
    const float* gru_b_hh = (const float*)d_in[9];
    const float* sg1_w    = (const float*)d_in[10];
    const float* sg1_b    = (const float*)d_in[11];
    const float* sg2_w    = (const float*)d_in[12];
    const float* sg2_b    = (const float*)d_in[13];
    const float* lg1_w    = (const float*)d_in[14];
    const float* lg1_b    = (const float*)d_in[15];
    const float* lg2_w    = (const float*)d_in[16];
    const float* lg2_b    = (const float*)d_in[17];
    float* out = (float*)d_out;

    int setup_elems = WROWS * NG + 3 * HH * HH;
    k_setup<<<(setup_elems + 255) / 256, 256>>>(gru_w_ih, gru_w_hh, sg1_w, lg1_w, h2h_w);
    k_conv<<<(int)(((size_t)BB * CC * TT / 4 + 255) / 256), 256>>>(fea);
    k_proj<<<dim3(TT / 64, HH / 64, BB), 256>>>(fea, i2h_w);
    k_decode<<<BB * 2, 1024>>>(targets, score_w,
                               gru_b_ih, gru_b_hh,
                               sg1_b, sg2_w, sg2_b,
                               lg1_b, lg2_w, lg2_b,
                               h2h_b, out);
}